// round 7
// baseline (speedup 1.0000x reference)
#include <cuda_runtime.h>
#include <math_constants.h>

// Problem dims
#define BATCH 64
#define DIM   768
#define MEM   2048
#define NCLS  1000

#define EC    48               // e-chunk per score unit (DIM/EC = 16)
#define NEC   (DIM / EC)
#define KC    32               // gemm k-chunk
#define NJT   6                // gemm j-tiles of 128
#define GEMM_UNITS (NJT * (DIM / KC))   // 144
#define SCORE_UNITS (2 * NEC * BATCH)   // 2048

#define GRIDN 592              // 4 CTAs/SM x 148 SMs: full wave-1, co-resident
#define NTHR  256

// Scratch (allocation-free)
__device__ float g_q[BATCH * DIM];
__device__ float g_t[BATCH * DIM];
__device__ float g_scores[BATCH * MEM];
__device__ unsigned g_bar[4];   // monotonic barrier counters (never reset)
__device__ unsigned g_ticket;   // score work ticket (reset each launch in P0)

// ---------------------------------------------------------------------------
// Grid-wide barrier for a co-resident grid. Monotonic counter: each arrival
// takes a ticket; generation g = old/GRIDN; release when count reaches
// (g+1)*GRIDN. Works unchanged across graph replays (no reset needed).
// ---------------------------------------------------------------------------
__device__ __forceinline__ void grid_barrier(unsigned* ctr) {
    __threadfence();          // make this thread's writes visible chip-wide
    __syncthreads();          // all threads of block arrived + fenced
    if (threadIdx.x == 0) {
        const unsigned t = atomicAdd(ctr, 1u);
        const unsigned target = (t / GRIDN + 1u) * GRIDN;
        while (*(volatile unsigned*)ctr < target) __nanosleep(128);
    }
    __syncthreads();
}

// ---------------------------------------------------------------------------
// GEMM phase: C[64,768] += A[64,768] @ W[768,768], split-K atomics.
// 144 units = 6 j-tiles(128) x 24 k-chunks(32); unit = blockIdx.x (<144).
// viaL2: read A with __ldcg (A was written by a previous phase; L1 not coherent).
// ---------------------------------------------------------------------------
__device__ void gemm_phase(const float* __restrict__ A,
                           const float* __restrict__ W,
                           float* __restrict__ C, bool viaL2) {
    const int u = blockIdx.x;
    if (u >= GEMM_UNITS) return;
    const int jt = u % NJT;
    const int k0 = (u / NJT) * KC;

    __shared__ float xs[KC][BATCH + 1];

    for (int i = threadIdx.x; i < BATCH * KC; i += NTHR) {
        const int b = i >> 5;
        const int d = i & 31;
        xs[d][b] = viaL2 ? __ldcg(&A[b * DIM + k0 + d]) : A[b * DIM + k0 + d];
    }
    __syncthreads();

    const int jv = threadIdx.x & 31;
    const int bg = threadIdx.x >> 5;
    const int j  = jt * 128 + jv * 4;

    float acc[8][4];
    #pragma unroll
    for (int bb = 0; bb < 8; bb++)
        #pragma unroll
        for (int jj = 0; jj < 4; jj++) acc[bb][jj] = 0.0f;

    #pragma unroll 4
    for (int d = 0; d < KC; d++) {
        const float4 w = *(const float4*)&W[(size_t)(k0 + d) * DIM + j];
        #pragma unroll
        for (int bb = 0; bb < 8; bb++) {
            const float xv = xs[d][bg * 8 + bb];
            acc[bb][0] = fmaf(xv, w.x, acc[bb][0]);
            acc[bb][1] = fmaf(xv, w.y, acc[bb][1]);
            acc[bb][2] = fmaf(xv, w.z, acc[bb][2]);
            acc[bb][3] = fmaf(xv, w.w, acc[bb][3]);
        }
    }

    #pragma unroll
    for (int bb = 0; bb < 8; bb++) {
        const int b = bg * 8 + bb;
        atomicAdd(&C[b * DIM + j + 0], acc[bb][0]);
        atomicAdd(&C[b * DIM + j + 1], acc[bb][1]);
        atomicAdd(&C[b * DIM + j + 2], acc[bb][2]);
        atomicAdd(&C[b * DIM + j + 3], acc[bb][3]);
    }
    __syncthreads();   // xs safe for the next gemm_phase call
}

// ---------------------------------------------------------------------------
// Score phase (dominant, HBM-bound): scores[b,m] += sum_e t[b,e]*mem[b,e,m].
// 2048 units = (2 m-tiles of 1024) x 16 e-chunks x 64 b, pulled dynamically
// via a global ticket (work stealing -> balanced tail).
// ---------------------------------------------------------------------------
__device__ void score_phase(const float* __restrict__ mem) {
    __shared__ float ts[EC];
    __shared__ unsigned sh_u;

    while (true) {
        if (threadIdx.x == 0) sh_u = atomicAdd(&g_ticket, 1u);
        __syncthreads();
        const unsigned u = sh_u;
        if (u >= SCORE_UNITS) break;   // uniform across block

        const int b  = u & 63;
        const int ey = (u >> 6) & 15;
        const int mt = u >> 10;
        const int e0 = ey * EC;

        if (threadIdx.x < EC) ts[threadIdx.x] = __ldcg(&g_t[b * DIM + e0 + threadIdx.x]);
        __syncthreads();

        const int m = mt * 1024 + threadIdx.x * 4;
        const float4* mp = (const float4*)(mem + (size_t)b * DIM * MEM
                                               + (size_t)e0 * MEM + m);

        float ax = 0.f, ay = 0.f, az = 0.f, aw = 0.f;
        #pragma unroll 8
        for (int e = 0; e < EC; e++) {
            const float4 v = __ldcs(&mp[(size_t)e * (MEM / 4)]);
            const float w = ts[e];
            ax = fmaf(w, v.x, ax);
            ay = fmaf(w, v.y, ay);
            az = fmaf(w, v.z, az);
            aw = fmaf(w, v.w, aw);
        }

        float* sp = &g_scores[b * MEM + m];
        atomicAdd(sp + 0, ax);
        atomicAdd(sp + 1, ay);
        atomicAdd(sp + 2, az);
        atomicAdd(sp + 3, aw);
        __syncthreads();   // ts / sh_u safe for next unit
    }
}

// ---------------------------------------------------------------------------
// Epilogue phase: blocks 0..63, one batch row each. leaky-relu + scatter into
// shared logits[1000] (smem atomics), softmax, write out.
// ---------------------------------------------------------------------------
__device__ void epilogue_phase(const int* __restrict__ lab32,
                               float* __restrict__ out) {
    const int b = blockIdx.x;
    const int tid = threadIdx.x;

    __shared__ float logits[NCLS];
    __shared__ float red[8];
    __shared__ int   sh_is64;

    for (int i = tid; i < NCLS; i += NTHR) logits[i] = 0.0f;
    if (tid == 0) {
        int any = 0;
        #pragma unroll
        for (int k = 0; k < 32; k++) any |= lab32[2 * k + 1];
        sh_is64 = (any == 0) ? 1 : 0;
    }
    __syncthreads();
    const int is64 = sh_is64;

    for (int i = tid; i < MEM; i += NTHR) {
        const size_t idx = (size_t)b * MEM + i;
        const float s = __ldcg(&g_scores[idx]);
        const float sv = (s >= 0.0f) ? s : 0.01f * s;
        int lab = is64 ? lab32[2 * idx] : lab32[idx];
        lab = min(max(lab, 0), NCLS - 1);
        atomicAdd(&logits[lab], sv);
    }
    __syncthreads();

    // --- max ---
    float mx = -CUDART_INF_F;
    for (int i = tid; i < NCLS; i += NTHR) mx = fmaxf(mx, logits[i]);
    #pragma unroll
    for (int o = 16; o > 0; o >>= 1) mx = fmaxf(mx, __shfl_xor_sync(0xffffffffu, mx, o));
    if ((tid & 31) == 0) red[tid >> 5] = mx;
    __syncthreads();
    if (tid < 32) {
        float v = (tid < 8) ? red[tid] : -CUDART_INF_F;
        #pragma unroll
        for (int o = 4; o > 0; o >>= 1) v = fmaxf(v, __shfl_xor_sync(0xffffffffu, v, o));
        if (tid == 0) red[0] = v;
    }
    __syncthreads();
    mx = red[0];
    __syncthreads();

    // --- exp + sum ---
    float sum = 0.0f;
    for (int i = tid; i < NCLS; i += NTHR) {
        const float e = __expf(logits[i] - mx);
        logits[i] = e;
        sum += e;
    }
    #pragma unroll
    for (int o = 16; o > 0; o >>= 1) sum += __shfl_xor_sync(0xffffffffu, sum, o);
    if ((tid & 31) == 0) red[tid >> 5] = sum;
    __syncthreads();
    if (tid < 32) {
        float v = (tid < 8) ? red[tid] : 0.0f;
        #pragma unroll
        for (int o = 4; o > 0; o >>= 1) v += __shfl_xor_sync(0xffffffffu, v, o);
        if (tid == 0) red[0] = v;
    }
    __syncthreads();
    const float inv = 1.0f / red[0];

    for (int i = tid; i < NCLS; i += NTHR) out[b * NCLS + i] = logits[i] * inv;
}

// ---------------------------------------------------------------------------
// Single persistent kernel: P0 zero -> P1 q=x@W_K -> P2 t=q@W_Q ->
// P3 score -> P4 epilogue, separated by software grid barriers.
// ---------------------------------------------------------------------------
__global__ void __launch_bounds__(NTHR, 4) fused_all(
    const float* __restrict__ x, const float* __restrict__ mem,
    const int* __restrict__ lab32,
    const float* __restrict__ W_Q, const float* __restrict__ W_K,
    float* __restrict__ out)
{
    // P0: zero scratch + reset ticket
    const float4 z = make_float4(0.f, 0.f, 0.f, 0.f);
    {
        const int i = blockIdx.x * NTHR + threadIdx.x;
        if (i < BATCH * DIM / 4) {
            ((float4*)g_q)[i] = z;
            ((float4*)g_t)[i] = z;
        }
        if (i < BATCH * MEM / 4) ((float4*)g_scores)[i] = z;
        if (blockIdx.x == 0 && threadIdx.x == 0) g_ticket = 0u;
    }
    grid_barrier(&g_bar[0]);

    gemm_phase(x, W_K, g_q, false);     // P1: q = x @ W_K
    grid_barrier(&g_bar[1]);

    gemm_phase(g_q, W_Q, g_t, true);    // P2: t = q @ W_Q
    grid_barrier(&g_bar[2]);

    score_phase(mem);                   // P3: dominant streaming phase
    grid_barrier(&g_bar[3]);

    if (blockIdx.x < BATCH) epilogue_phase(lab32, out);  // P4
}

// ---------------------------------------------------------------------------
// Launch: ONE kernel. Inputs mapped by element count: x 49152, mem 100663296,
// labels 131072, W_Q / W_K 589824 each (W_Q first). Output: f32[64,1000].
// ---------------------------------------------------------------------------
extern "C" void kernel_launch(void* const* d_in, const int* in_sizes, int n_in,
                              void* d_out, int out_size) {
    const float* x   = nullptr;
    const float* mem = nullptr;
    const int* labs  = nullptr;
    const float* W_Q = nullptr;
    const float* W_K = nullptr;

    for (int i = 0; i < n_in; i++) {
        const int sz = in_sizes[i];
        if (sz == BATCH * DIM)            x    = (const float*)d_in[i];
        else if (sz == BATCH * DIM * MEM) mem  = (const float*)d_in[i];
        else if (sz == BATCH * MEM)       labs = (const int*)d_in[i];
        else if (sz == DIM * DIM) {
            if (!W_Q) W_Q = (const float*)d_in[i];
            else      W_K = (const float*)d_in[i];
        }
    }
    float* out = (float*)d_out;

    fused_all<<<GRIDN, NTHR>>>(x, mem, labs, W_Q, W_K, out);
}